// round 3
// baseline (speedup 1.0000x reference)
#include <cuda_runtime.h>

#define NN   100000
#define FF   128
#define HH   4
#define EE   3200000
#define QKC  1024   // 2*H*F channels per node

// Scratch (allocation-free: device globals)
__device__ float g_qk[(size_t)NN * QKC];       // [N][H][2F]: q at h*256+f, k at h*256+128+f
__device__ float g_scores[(size_t)EE * HH];    // per-edge per-head scores -> exp()
__device__ int   g_max[NN * HH];               // ordered-int encoded float max per (node, head)
__device__ float g_sum[NN * HH];               // exp-sum per (node, head)
__device__ int   g_is64;                       // 1 if edge_index is int64, 0 if int32

// ---------------- dtype detection (device-side, graph-capturable) ----------------
__global__ void detect_kernel(const void* __restrict__ ei) {
    // Indices are in [0, 100000): if the buffer is int64, every odd int32 word
    // (upper half) is 0. If int32, odd words are real indices (P(==0) = 1e-5 each).
    const int2* p = (const int2*)ei;
    int is64 = 1;
    for (int i = 0; i < 1024; i++) {
        if (p[i].y != 0) { is64 = 0; break; }
    }
    g_is64 = is64;
}

__device__ __forceinline__ int load_idx(const void* __restrict__ ei, size_t i, int is64) {
    if (is64) return (int)((const long long*)ei)[i];
    return ((const int*)ei)[i];
}

// ---------------- init ----------------
__global__ void init_kernel() {
    int i = blockIdx.x * blockDim.x + threadIdx.x;
    if (i < NN * HH) {
        g_max[i] = (int)0x80000000;
        g_sum[i] = 0.0f;
    }
}

// ---------------- GEMM: qk = x @ W.T + b ----------------
#define BM 64
#define BN 64
#define BK 32

__global__ void gemm_kernel(const float* __restrict__ x,
                            const float* __restrict__ W,
                            const float* __restrict__ bias) {
    __shared__ float As[BK][BM + 1];
    __shared__ float Bs[BK][BN + 1];

    int tid = threadIdx.x;           // 256 threads
    int nb = blockIdx.x * BM;
    int jb = blockIdx.y * BN;
    int tx = tid & 15;
    int ty = tid >> 4;

    int lm = tid >> 3;               // 0..31
    int lk = (tid & 7) << 2;         // 0,4,...,28

    float acc[4][4];
    #pragma unroll
    for (int i = 0; i < 4; i++)
        #pragma unroll
        for (int j = 0; j < 4; j++) acc[i][j] = 0.0f;

    for (int kb = 0; kb < FF; kb += BK) {
        #pragma unroll
        for (int s = 0; s < 2; s++) {
            int m = lm + s * 32;
            int gr = nb + m;
            float4 v = make_float4(0.f, 0.f, 0.f, 0.f);
            if (gr < NN) v = *(const float4*)(x + (size_t)gr * FF + kb + lk);
            As[lk + 0][m] = v.x; As[lk + 1][m] = v.y;
            As[lk + 2][m] = v.z; As[lk + 3][m] = v.w;
        }
        #pragma unroll
        for (int s = 0; s < 2; s++) {
            int n = lm + s * 32;
            float4 v = *(const float4*)(W + (size_t)(jb + n) * FF + kb + lk);
            Bs[lk + 0][n] = v.x; Bs[lk + 1][n] = v.y;
            Bs[lk + 2][n] = v.z; Bs[lk + 3][n] = v.w;
        }
        __syncthreads();

        #pragma unroll
        for (int k = 0; k < BK; k++) {
            float a[4], bb[4];
            #pragma unroll
            for (int i = 0; i < 4; i++) a[i] = As[k][ty * 4 + i];
            #pragma unroll
            for (int j = 0; j < 4; j++) bb[j] = Bs[k][tx * 4 + j];
            #pragma unroll
            for (int i = 0; i < 4; i++)
                #pragma unroll
                for (int j = 0; j < 4; j++)
                    acc[i][j] += a[i] * bb[j];
        }
        __syncthreads();
    }

    #pragma unroll
    for (int i = 0; i < 4; i++) {
        int gr = nb + ty * 4 + i;
        if (gr < NN) {
            #pragma unroll
            for (int j = 0; j < 4; j++) {
                int gc = jb + tx * 4 + j;
                g_qk[(size_t)gr * QKC + gc] = acc[i][j] + bias[gc];
            }
        }
    }
}

// ---------------- scores: warp per edge ----------------
__device__ __forceinline__ int enc_float(float f) {
    int i = __float_as_int(f);
    return (i >= 0) ? i : (i ^ 0x7FFFFFFF);
}
__device__ __forceinline__ float dec_float(int i) {
    return __int_as_float((i >= 0) ? i : (i ^ 0x7FFFFFFF));
}

__global__ void score_kernel(const void* __restrict__ ei) {
    int warp = (blockIdx.x * blockDim.x + threadIdx.x) >> 5;
    int lane = threadIdx.x & 31;
    if (warp >= EE) return;

    int is64 = g_is64;
    int row = load_idx(ei, warp, is64);
    int col = load_idx(ei, (size_t)EE + warp, is64);
    if ((unsigned)row >= NN || (unsigned)col >= NN) return;  // safety: no IMA

    const float4* qb = (const float4*)(g_qk + (size_t)row * QKC);
    const float4* kb = (const float4*)(g_qk + (size_t)col * QKC);

    float acc[HH];
    #pragma unroll
    for (int h = 0; h < HH; h++) {
        float4 qv = qb[h * 64 + lane];
        float4 kv = kb[h * 64 + 32 + lane];
        acc[h] = qv.x * kv.x + qv.y * kv.y + qv.z * kv.z + qv.w * kv.w;
    }
    #pragma unroll
    for (int h = 0; h < HH; h++) {
        #pragma unroll
        for (int o = 16; o; o >>= 1)
            acc[h] += __shfl_xor_sync(0xffffffffu, acc[h], o);
    }
    if (lane == 0) {
        *(float4*)(g_scores + (size_t)warp * HH) =
            make_float4(acc[0], acc[1], acc[2], acc[3]);
        #pragma unroll
        for (int h = 0; h < HH; h++)
            atomicMax(&g_max[row * HH + h], enc_float(acc[h]));
    }
}

// ---------------- exp + segment sum ----------------
__global__ void exp_kernel(const void* __restrict__ ei) {
    int idx = blockIdx.x * blockDim.x + threadIdx.x;
    if (idx >= EE * HH) return;
    int e = idx >> 2;
    int h = idx & 3;
    int row = load_idx(ei, e, g_is64);
    if ((unsigned)row >= NN) return;
    float mx = dec_float(g_max[row * HH + h]);
    float ex = expf(g_scores[idx] - mx);
    g_scores[idx] = ex;
    atomicAdd(&g_sum[row * HH + h], ex);
}

// ---------------- normalize + head mean ----------------
__global__ void final_kernel(const void* __restrict__ ei,
                             float* __restrict__ out) {
    int e = blockIdx.x * blockDim.x + threadIdx.x;
    if (e >= EE) return;
    int row = load_idx(ei, e, g_is64);
    if ((unsigned)row >= NN) { out[e] = 0.0f; return; }
    float4 sc = *(const float4*)(g_scores + (size_t)e * HH);
    float4 sm = *(const float4*)(g_sum + row * HH);
    out[e] = 0.25f * (sc.x / sm.x + sc.y / sm.y + sc.z / sm.z + sc.w / sm.w);
}

// ---------------- launch ----------------
extern "C" void kernel_launch(void* const* d_in, const int* in_sizes, int n_in,
                              void* d_out, int out_size) {
    // Identify inputs by element count (order-proof):
    //   x: 100000*128 = 12800000,  W: 1024*128 = 131072,  b: 1024,
    //   edge_index: 2*3200000 = 6400000 (int32 OR int64 -> device-side detect)
    const float* x    = nullptr;
    const float* W    = nullptr;
    const float* bias = nullptr;
    const void*  ei   = nullptr;
    for (int i = 0; i < n_in; i++) {
        long long sz = in_sizes[i];
        if      (sz == (long long)NN * FF)  x    = (const float*)d_in[i];
        else if (sz == (long long)QKC * FF) W    = (const float*)d_in[i];
        else if (sz == (long long)QKC)      bias = (const float*)d_in[i];
        else if (sz == 2LL * EE)            ei   = d_in[i];
    }
    // fallback to documented order if size matching ever fails
    if (!x)    x    = (const float*)d_in[0];
    if (!W)    W    = (const float*)d_in[1];
    if (!bias) bias = (const float*)d_in[2];
    if (!ei)   ei   = d_in[3];
    float* out = (float*)d_out;

    detect_kernel<<<1, 1>>>(ei);

    init_kernel<<<(NN * HH + 255) / 256, 256>>>();

    dim3 ggrid((NN + BM - 1) / BM, QKC / BN);
    gemm_kernel<<<ggrid, 256>>>(x, W, bias);

    int score_blocks = (EE * 32 + 255) / 256;   // one warp per edge
    score_kernel<<<score_blocks, 256>>>(ei);

    exp_kernel<<<(EE * HH + 255) / 256, 256>>>(ei);

    final_kernel<<<(EE + 255) / 256, 256>>>(ei, out);
}

// round 4
// speedup vs baseline: 1.4720x; 1.4720x over previous
#include <cuda_runtime.h>
#include <math_constants.h>

#define NN   100000
#define FF   128
#define HH   4
#define EE   3200000
#define QKC  1024
#define HF   512            // H*F floats per node (q or k)
#define NB_SCAN ((NN + 1023) / 1024)   // 98

// ---------------- device scratch (allocation-free) ----------------
__device__ float g_q[(size_t)NN * HF];        // [N][H][F]
__device__ float g_k[(size_t)NN * HF];        // [N][H][F]
__device__ float g_ssc[(size_t)EE * HH];      // scores in sorted-edge order
__device__ int   g_scol[EE];                  // sorted: col per position
__device__ int   g_sorig[EE];                 // sorted: original edge id
__device__ int   g_cnt[NN];                   // edges per row
__device__ int   g_start[NN];                 // exclusive prefix (segment start)
__device__ int   g_cursor[NN];                // scatter cursor
__device__ int   g_bsum[NB_SCAN + 32];
__device__ int   g_is64;

// ---------------- edge dtype detect ----------------
__global__ void detect_kernel(const void* __restrict__ ei) {
    const int2* p = (const int2*)ei;
    int is64 = 1;
    for (int i = 0; i < 1024; i++)
        if (p[i].y != 0) { is64 = 0; break; }
    g_is64 = is64;
}
__device__ __forceinline__ int load_idx(const void* __restrict__ ei, size_t i, int is64) {
    if (is64) return (int)((const long long*)ei)[i];
    return ((const int*)ei)[i];
}

// ---------------- init ----------------
__global__ void init_kernel() {
    int i = blockIdx.x * blockDim.x + threadIdx.x;
    if (i < NN) g_cnt[i] = 0;
}

// ---------------- GEMM: qk = x @ W.T + b, split into q/k tables ----------------
#define BM 64
#define BN 64
#define BK 32

__global__ void gemm_kernel(const float* __restrict__ x,
                            const float* __restrict__ W,
                            const float* __restrict__ bias) {
    __shared__ float As[BK][BM + 1];
    __shared__ float Bs[BK][BN + 1];

    int tid = threadIdx.x;
    int nb = blockIdx.x * BM;
    int jb = blockIdx.y * BN;
    int tx = tid & 15;
    int ty = tid >> 4;
    int lm = tid >> 3;
    int lk = (tid & 7) << 2;

    float acc[4][4];
    #pragma unroll
    for (int i = 0; i < 4; i++)
        #pragma unroll
        for (int j = 0; j < 4; j++) acc[i][j] = 0.0f;

    for (int kb = 0; kb < FF; kb += BK) {
        #pragma unroll
        for (int s = 0; s < 2; s++) {
            int m = lm + s * 32;
            int gr = nb + m;
            float4 v = make_float4(0.f, 0.f, 0.f, 0.f);
            if (gr < NN) v = *(const float4*)(x + (size_t)gr * FF + kb + lk);
            As[lk + 0][m] = v.x; As[lk + 1][m] = v.y;
            As[lk + 2][m] = v.z; As[lk + 3][m] = v.w;
        }
        #pragma unroll
        for (int s = 0; s < 2; s++) {
            int n = lm + s * 32;
            float4 v = *(const float4*)(W + (size_t)(jb + n) * FF + kb + lk);
            Bs[lk + 0][n] = v.x; Bs[lk + 1][n] = v.y;
            Bs[lk + 2][n] = v.z; Bs[lk + 3][n] = v.w;
        }
        __syncthreads();

        #pragma unroll
        for (int k = 0; k < BK; k++) {
            float a[4], bb[4];
            #pragma unroll
            for (int i = 0; i < 4; i++) a[i] = As[k][ty * 4 + i];
            #pragma unroll
            for (int j = 0; j < 4; j++) bb[j] = Bs[k][tx * 4 + j];
            #pragma unroll
            for (int i = 0; i < 4; i++)
                #pragma unroll
                for (int j = 0; j < 4; j++)
                    acc[i][j] += a[i] * bb[j];
        }
        __syncthreads();
    }

    #pragma unroll
    for (int i = 0; i < 4; i++) {
        int gr = nb + ty * 4 + i;
        if (gr < NN) {
            #pragma unroll
            for (int j = 0; j < 4; j++) {
                int gc = jb + tx * 4 + j;
                float v = acc[i][j] + bias[gc];
                int h = gc >> 8;          // head
                int r = gc & 255;         // channel within head (q:0..127, k:128..255)
                if (r < FF) g_q[(size_t)gr * HF + h * FF + r] = v;
                else        g_k[(size_t)gr * HF + h * FF + (r - FF)] = v;
            }
        }
    }
}

// ---------------- counting sort of edges by row ----------------
__global__ void hist_kernel(const void* __restrict__ ei) {
    int e = blockIdx.x * blockDim.x + threadIdx.x;
    if (e >= EE) return;
    int row = load_idx(ei, e, g_is64);
    if ((unsigned)row < NN) atomicAdd(&g_cnt[row], 1);
}

__global__ void scan1_kernel() {   // 1024 threads/block, NB_SCAN blocks
    __shared__ int sm[1024];
    int tid = threadIdx.x;
    int i = blockIdx.x * 1024 + tid;
    int val = (i < NN) ? g_cnt[i] : 0;
    sm[tid] = val;
    __syncthreads();
    #pragma unroll
    for (int o = 1; o < 1024; o <<= 1) {
        int t = (tid >= o) ? sm[tid - o] : 0;
        __syncthreads();
        sm[tid] += t;
        __syncthreads();
    }
    if (i < NN) g_start[i] = sm[tid] - val;       // exclusive within block
    if (tid == 1023) g_bsum[blockIdx.x] = sm[tid];
}

__global__ void scan2_kernel() {   // single block of 128 threads
    __shared__ int sm[128];
    int tid = threadIdx.x;
    int val = (tid < NB_SCAN) ? g_bsum[tid] : 0;
    sm[tid] = val;
    __syncthreads();
    #pragma unroll
    for (int o = 1; o < 128; o <<= 1) {
        int t = (tid >= o) ? sm[tid - o] : 0;
        __syncthreads();
        sm[tid] += t;
        __syncthreads();
    }
    g_bsum[tid] = sm[tid] - val;                  // exclusive block offsets
}

__global__ void scan3_kernel() {
    int i = blockIdx.x * blockDim.x + threadIdx.x;
    if (i >= NN) return;
    int s = g_start[i] + g_bsum[i >> 10];
    g_start[i] = s;
    g_cursor[i] = s;
}

__global__ void scatter_kernel(const void* __restrict__ ei) {
    int e = blockIdx.x * blockDim.x + threadIdx.x;
    if (e >= EE) return;
    int is64 = g_is64;
    int row = load_idx(ei, e, is64);
    int col = load_idx(ei, (size_t)EE + e, is64);
    if ((unsigned)row >= NN || (unsigned)col >= NN) return;
    int pos = atomicAdd(&g_cursor[row], 1);
    g_scol[pos] = col;
    g_sorig[pos] = e;
}

// ---------------- fused attention: warp per node ----------------
__device__ __forceinline__ float wred(float v) {
    #pragma unroll
    for (int o = 16; o; o >>= 1) v += __shfl_xor_sync(0xffffffffu, v, o);
    return v;
}

__global__ void attn_kernel(float* __restrict__ out) {
    int warp = (blockIdx.x * blockDim.x + threadIdx.x) >> 5;
    int lane = threadIdx.x & 31;
    if (warp >= NN) return;
    int cnt = g_cnt[warp];
    if (cnt == 0) return;
    int beg = g_start[warp];

    // q for this node: lane holds floats [h*128 + lane*4 .. +3] for each head
    const float4* qb = (const float4*)(g_q + (size_t)warp * HF);
    float4 q[HH];
    #pragma unroll
    for (int h = 0; h < HH; h++) q[h] = qb[h * 32 + lane];

    float m[HH];
    #pragma unroll
    for (int h = 0; h < HH; h++) m[h] = -CUDART_INF_F;

    // pass 1: compute scores (gather k), track max, store scores per segment
    for (int j = 0; j < cnt; j++) {
        int col = g_scol[beg + j];
        const float4* kb = (const float4*)(g_k + (size_t)col * HF);
        float sc[HH];
        #pragma unroll
        for (int h = 0; h < HH; h++) {
            float4 kv = kb[h * 32 + lane];
            sc[h] = q[h].x * kv.x + q[h].y * kv.y + q[h].z * kv.z + q[h].w * kv.w;
        }
        #pragma unroll
        for (int h = 0; h < HH; h++) {
            sc[h] = wred(sc[h]);                  // butterfly: all lanes get it
            m[h] = fmaxf(m[h], sc[h]);
        }
        if (lane == 0)
            *(float4*)(g_ssc + (size_t)(beg + j) * HH) =
                make_float4(sc[0], sc[1], sc[2], sc[3]);
    }

    // pass 2: exp-sum (scores are L1/L2 hot, lane-parallel)
    float s[HH] = {0.f, 0.f, 0.f, 0.f};
    for (int j = lane; j < cnt; j += 32) {
        float4 sc = *(const float4*)(g_ssc + (size_t)(beg + j) * HH);
        s[0] += __expf(sc.x - m[0]);
        s[1] += __expf(sc.y - m[1]);
        s[2] += __expf(sc.z - m[2]);
        s[3] += __expf(sc.w - m[3]);
    }
    #pragma unroll
    for (int h = 0; h < HH; h++) s[h] = wred(s[h]);
    float inv[HH];
    #pragma unroll
    for (int h = 0; h < HH; h++) inv[h] = 1.0f / s[h];

    // pass 3: normalize + head-mean, scatter to original edge order
    for (int j = lane; j < cnt; j += 32) {
        float4 sc = *(const float4*)(g_ssc + (size_t)(beg + j) * HH);
        int orig = g_sorig[beg + j];
        out[orig] = 0.25f * (__expf(sc.x - m[0]) * inv[0] +
                             __expf(sc.y - m[1]) * inv[1] +
                             __expf(sc.z - m[2]) * inv[2] +
                             __expf(sc.w - m[3]) * inv[3]);
    }
}

// ---------------- launch ----------------
extern "C" void kernel_launch(void* const* d_in, const int* in_sizes, int n_in,
                              void* d_out, int out_size) {
    const float* x    = nullptr;
    const float* W    = nullptr;
    const float* bias = nullptr;
    const void*  ei   = nullptr;
    for (int i = 0; i < n_in; i++) {
        long long sz = in_sizes[i];
        if      (sz == (long long)NN * FF)  x    = (const float*)d_in[i];
        else if (sz == (long long)QKC * FF) W    = (const float*)d_in[i];
        else if (sz == (long long)QKC)      bias = (const float*)d_in[i];
        else if (sz == 2LL * EE)            ei   = d_in[i];
    }
    if (!x)    x    = (const float*)d_in[0];
    if (!W)    W    = (const float*)d_in[1];
    if (!bias) bias = (const float*)d_in[2];
    if (!ei)   ei   = d_in[3];
    float* out = (float*)d_out;

    detect_kernel<<<1, 1>>>(ei);
    init_kernel<<<(NN + 255) / 256, 256>>>();

    dim3 ggrid((NN + BM - 1) / BM, QKC / BN);
    gemm_kernel<<<ggrid, 256>>>(x, W, bias);

    hist_kernel<<<(EE + 255) / 256, 256>>>(ei);
    scan1_kernel<<<NB_SCAN, 1024>>>();
    scan2_kernel<<<1, 128>>>();
    scan3_kernel<<<(NN + 255) / 256, 256>>>();
    scatter_kernel<<<(EE + 255) / 256, 256>>>(ei);

    attn_kernel<<<(NN * 32 + 255) / 256, 256>>>(out);
}

// round 6
// speedup vs baseline: 1.6516x; 1.1220x over previous
#include <cuda_runtime.h>
#include <math_constants.h>

#define NN   100000
#define FF   128
#define HH   4
#define EE   3200000
#define QKC  1024
#define HF   512              // H*F floats per node (q or k)
#define NBLK 4                // col blocks (32768 nodes -> 64MB k slice, L2-resident)
#define CSH  15               // col >> 15
#define NBINS (NN * NBLK)     // 400000
#define NB2  ((NBINS + 1023) / 1024)   // 391

// ---------------- device scratch (allocation-free) ----------------
__device__ float g_q[(size_t)NN * HF];        // [N][H][F]
__device__ float g_k[(size_t)NN * HF];        // [N][H][F]
__device__ float g_ssc[(size_t)EE * HH];      // scores in sorted order
__device__ int   g_scol[EE];                  // sorted: col
__device__ int   g_sorig[EE];                 // sorted: original edge id
__device__ int   g_cnt[NBINS];                // edges per (row, colblk) bin
__device__ int   g_start[NBINS];              // exclusive prefix
__device__ int   g_cursor[NBINS];
__device__ int   g_bsum[1024];                // FIX: was NB2+32; scan2's 512 threads overran it
__device__ int   g_is64;

// ---------------- edge dtype detect ----------------
__global__ void detect_kernel(const void* __restrict__ ei) {
    const int2* p = (const int2*)ei;
    int is64 = 1;
    for (int i = 0; i < 1024; i++)
        if (p[i].y != 0) { is64 = 0; break; }
    g_is64 = is64;
}
__device__ __forceinline__ int load_idx(const void* __restrict__ ei, size_t i, int is64) {
    if (is64) return (int)((const long long*)ei)[i];
    return ((const int*)ei)[i];
}

// ---------------- init ----------------
__global__ void init_kernel() {
    int i = blockIdx.x * blockDim.x + threadIdx.x;
    if (i < NBINS) g_cnt[i] = 0;
}

// ---------------- GEMM: qk = x @ W.T + b, split into q/k tables ----------------
#define BM 64
#define BN 64
#define BK 32

__global__ void gemm_kernel(const float* __restrict__ x,
                            const float* __restrict__ W,
                            const float* __restrict__ bias) {
    __shared__ float As[BK][BM + 1];
    __shared__ float Bs[BK][BN + 1];

    int tid = threadIdx.x;
    int nb = blockIdx.x * BM;
    int jb = blockIdx.y * BN;
    int tx = tid & 15;
    int ty = tid >> 4;
    int lm = tid >> 3;
    int lk = (tid & 7) << 2;

    float acc[4][4];
    #pragma unroll
    for (int i = 0; i < 4; i++)
        #pragma unroll
        for (int j = 0; j < 4; j++) acc[i][j] = 0.0f;

    for (int kb = 0; kb < FF; kb += BK) {
        #pragma unroll
        for (int s = 0; s < 2; s++) {
            int m = lm + s * 32;
            int gr = nb + m;
            float4 v = make_float4(0.f, 0.f, 0.f, 0.f);
            if (gr < NN) v = *(const float4*)(x + (size_t)gr * FF + kb + lk);
            As[lk + 0][m] = v.x; As[lk + 1][m] = v.y;
            As[lk + 2][m] = v.z; As[lk + 3][m] = v.w;
        }
        #pragma unroll
        for (int s = 0; s < 2; s++) {
            int n = lm + s * 32;
            float4 v = *(const float4*)(W + (size_t)(jb + n) * FF + kb + lk);
            Bs[lk + 0][n] = v.x; Bs[lk + 1][n] = v.y;
            Bs[lk + 2][n] = v.z; Bs[lk + 3][n] = v.w;
        }
        __syncthreads();

        #pragma unroll
        for (int k = 0; k < BK; k++) {
            float a[4], bb[4];
            #pragma unroll
            for (int i = 0; i < 4; i++) a[i] = As[k][ty * 4 + i];
            #pragma unroll
            for (int j = 0; j < 4; j++) bb[j] = Bs[k][tx * 4 + j];
            #pragma unroll
            for (int i = 0; i < 4; i++)
                #pragma unroll
                for (int j = 0; j < 4; j++)
                    acc[i][j] += a[i] * bb[j];
        }
        __syncthreads();
    }

    #pragma unroll
    for (int i = 0; i < 4; i++) {
        int gr = nb + ty * 4 + i;
        if (gr < NN) {
            #pragma unroll
            for (int j = 0; j < 4; j++) {
                int gc = jb + tx * 4 + j;
                float v = acc[i][j] + bias[gc];
                int h = gc >> 8;
                int r = gc & 255;
                if (r < FF) g_q[(size_t)gr * HF + h * FF + r] = v;
                else        g_k[(size_t)gr * HF + h * FF + (r - FF)] = v;
            }
        }
    }
}

// ---------------- counting sort of edges by (row, colblk) ----------------
__global__ void hist_kernel(const void* __restrict__ ei) {
    int e = blockIdx.x * blockDim.x + threadIdx.x;
    if (e >= EE) return;
    int is64 = g_is64;
    int row = load_idx(ei, e, is64);
    int col = load_idx(ei, (size_t)EE + e, is64);
    if ((unsigned)row >= NN || (unsigned)col >= NN) return;
    atomicAdd(&g_cnt[row * NBLK + (col >> CSH)], 1);
}

__global__ void scan1_kernel() {   // 1024 threads/block
    __shared__ int sm[1024];
    int tid = threadIdx.x;
    int i = blockIdx.x * 1024 + tid;
    int val = (i < NBINS) ? g_cnt[i] : 0;
    sm[tid] = val;
    __syncthreads();
    #pragma unroll
    for (int o = 1; o < 1024; o <<= 1) {
        int t = (tid >= o) ? sm[tid - o] : 0;
        __syncthreads();
        sm[tid] += t;
        __syncthreads();
    }
    if (i < NBINS) g_start[i] = sm[tid] - val;
    if (tid == 1023) g_bsum[blockIdx.x] = sm[tid];
}

__global__ void scan2_kernel() {   // single block of 512 threads
    __shared__ int sm[512];
    int tid = threadIdx.x;
    int val = (tid < NB2) ? g_bsum[tid] : 0;
    sm[tid] = val;
    __syncthreads();
    #pragma unroll
    for (int o = 1; o < 512; o <<= 1) {
        int t = (tid >= o) ? sm[tid - o] : 0;
        __syncthreads();
        sm[tid] += t;
        __syncthreads();
    }
    if (tid < NB2) g_bsum[tid] = sm[tid] - val;   // FIX: guard the write
}

__global__ void scan3_kernel() {
    int i = blockIdx.x * blockDim.x + threadIdx.x;
    if (i >= NBINS) return;
    int s = g_start[i] + g_bsum[i >> 10];
    g_start[i] = s;
    g_cursor[i] = s;
}

__global__ void scatter_kernel(const void* __restrict__ ei) {
    int e = blockIdx.x * blockDim.x + threadIdx.x;
    if (e >= EE) return;
    int is64 = g_is64;
    int row = load_idx(ei, e, is64);
    int col = load_idx(ei, (size_t)EE + e, is64);
    if ((unsigned)row >= NN || (unsigned)col >= NN) return;
    int pos = atomicAdd(&g_cursor[row * NBLK + (col >> CSH)], 1);
    if ((unsigned)pos >= EE) return;              // defense in depth
    g_scol[pos] = col;
    g_sorig[pos] = e;
}

// ---------------- warp helpers ----------------
__device__ __forceinline__ float wred_sum(float v) {
    #pragma unroll
    for (int o = 16; o; o >>= 1) v += __shfl_xor_sync(0xffffffffu, v, o);
    return v;
}
__device__ __forceinline__ float wred_max(float v) {
    #pragma unroll
    for (int o = 16; o; o >>= 1) v = fmaxf(v, __shfl_xor_sync(0xffffffffu, v, o));
    return v;
}

// ---------------- score pass: warp per (colblk, row) segment ----------------
// warp id w: blk = w / NN, row = w % NN  -> CTA launch order walks col blocks
// sequentially, keeping the active 64MB k slice L2-resident.
__global__ void score_kernel() {
    int w = (blockIdx.x * blockDim.x + threadIdx.x) >> 5;
    int lane = threadIdx.x & 31;
    if (w >= NBINS) return;
    int blk = w / NN;
    int row = w - blk * NN;
    int bin = row * NBLK + blk;
    int cnt = g_cnt[bin];
    if (cnt == 0) return;
    int beg = g_start[bin];

    const float4* qb = (const float4*)(g_q + (size_t)row * HF);
    float4 q[HH];
    #pragma unroll
    for (int h = 0; h < HH; h++) q[h] = qb[h * 32 + lane];

    for (int j = 0; j < cnt; j++) {
        int col = g_scol[beg + j];
        const float4* kb = (const float4*)(g_k + (size_t)col * HF);
        float sc[HH];
        #pragma unroll
        for (int h = 0; h < HH; h++) {
            float4 kv = kb[h * 32 + lane];
            sc[h] = q[h].x * kv.x + q[h].y * kv.y + q[h].z * kv.z + q[h].w * kv.w;
        }
        #pragma unroll
        for (int h = 0; h < HH; h++) sc[h] = wred_sum(sc[h]);
        if (lane == 0)
            *(float4*)(g_ssc + (size_t)(beg + j) * HH) =
                make_float4(sc[0], sc[1], sc[2], sc[3]);
    }
}

// ---------------- softmax pass: warp per row (its 4 sub-segments are contiguous) ----------------
__global__ void softmax_kernel(float* __restrict__ out) {
    int row = (blockIdx.x * blockDim.x + threadIdx.x) >> 5;
    int lane = threadIdx.x & 31;
    if (row >= NN) return;
    int beg = g_start[row * NBLK];
    int end = g_start[row * NBLK + NBLK - 1] + g_cnt[row * NBLK + NBLK - 1];
    if (end <= beg) return;

    // max per head
    float m[HH] = {-CUDART_INF_F, -CUDART_INF_F, -CUDART_INF_F, -CUDART_INF_F};
    for (int j = beg + lane; j < end; j += 32) {
        float4 sc = *(const float4*)(g_ssc + (size_t)j * HH);
        m[0] = fmaxf(m[0], sc.x); m[1] = fmaxf(m[1], sc.y);
        m[2] = fmaxf(m[2], sc.z); m[3] = fmaxf(m[3], sc.w);
    }
    #pragma unroll
    for (int h = 0; h < HH; h++) m[h] = wred_max(m[h]);

    // exp-sum per head (scores L2-hot)
    float s[HH] = {0.f, 0.f, 0.f, 0.f};
    for (int j = beg + lane; j < end; j += 32) {
        float4 sc = *(const float4*)(g_ssc + (size_t)j * HH);
        s[0] += __expf(sc.x - m[0]);
        s[1] += __expf(sc.y - m[1]);
        s[2] += __expf(sc.z - m[2]);
        s[3] += __expf(sc.w - m[3]);
    }
    #pragma unroll
    for (int h = 0; h < HH; h++) s[h] = wred_sum(s[h]);
    float inv[HH];
    #pragma unroll
    for (int h = 0; h < HH; h++) inv[h] = 1.0f / s[h];

    // normalize + head mean, scatter to original edge ids
    for (int j = beg + lane; j < end; j += 32) {
        float4 sc = *(const float4*)(g_ssc + (size_t)j * HH);
        int orig = g_sorig[j];
        out[orig] = 0.25f * (__expf(sc.x - m[0]) * inv[0] +
                             __expf(sc.y - m[1]) * inv[1] +
                             __expf(sc.z - m[2]) * inv[2] +
                             __expf(sc.w - m[3]) * inv[3]);
    }
}

// ---------------- launch ----------------
extern "C" void kernel_launch(void* const* d_in, const int* in_sizes, int n_in,
                              void* d_out, int out_size) {
    const float* x    = nullptr;
    const float* W    = nullptr;
    const float* bias = nullptr;
    const void*  ei   = nullptr;
    for (int i = 0; i < n_in; i++) {
        long long sz = in_sizes[i];
        if      (sz == (long long)NN * FF)  x    = (const float*)d_in[i];
        else if (sz == (long long)QKC * FF) W    = (const float*)d_in[i];
        else if (sz == (long long)QKC)      bias = (const float*)d_in[i];
        else if (sz == 2LL * EE)            ei   = d_in[i];
    }
    if (!x)    x    = (const float*)d_in[0];
    if (!W)    W    = (const float*)d_in[1];
    if (!bias) bias = (const float*)d_in[2];
    if (!ei)   ei   = d_in[3];
    float* out = (float*)d_out;

    detect_kernel<<<1, 1>>>(ei);
    init_kernel<<<(NBINS + 255) / 256, 256>>>();

    dim3 ggrid((NN + BM - 1) / BM, QKC / BN);
    gemm_kernel<<<ggrid, 256>>>(x, W, bias);

    hist_kernel<<<(EE + 255) / 256, 256>>>(ei);
    scan1_kernel<<<NB2, 1024>>>();
    scan2_kernel<<<1, 512>>>();
    scan3_kernel<<<(NBINS + 255) / 256, 256>>>();
    scatter_kernel<<<(EE + 255) / 256, 256>>>(ei);

    score_kernel<<<((size_t)NBINS * 32 + 255) / 256, 256>>>();
    softmax_kernel<<<((size_t)NN * 32 + 255) / 256, 256>>>(out);
}